// round 2
// baseline (speedup 1.0000x reference)
#include <cuda_runtime.h>
#include <cuda_fp16.h>
#include <cuda_bf16.h>
#include <cstdint>
#include <cstddef>

#define TT   4096
#define HID  2048
#define INW  2048
#define G4   (4*HID)

#define NCTA     148
#define HPC      14
#define NROWS    (HPC*4)
#define RTHREADS 448
#define REC_SMEM (NROWS*HID*2)   // 229376 bytes of fp16 W_hh rows

// ---------------- scratch layout (single __device__ array) ----------------
#define OFF_GX    ((size_t)0)                            // float [T][4H]
#define OFF_XH    (OFF_GX   + (size_t)TT*G4*4)           // half  [T][I] hi
#define OFF_XL    (OFF_XH   + (size_t)TT*INW*2)          // half  [T][I] lo
#define OFF_WIH   (OFF_XL   + (size_t)TT*INW*2)          // half  [4H][I] hi
#define OFF_WIL   (OFF_WIH  + (size_t)G4*INW*2)          // half  [4H][I] lo
#define OFF_WO    (OFF_WIL  + (size_t)G4*INW*2)          // half  [I][H] hi
#define OFF_WOL   (OFF_WO   + (size_t)INW*HID*2)         // half  [I][H] lo (unused)
#define OFF_HS    (OFF_WOL  + (size_t)INW*HID*2)         // half  [T][H]
#define OFF_BIAS  (OFF_HS   + (size_t)TT*HID*2)          // float [4H]
#define OFF_HBUF  (OFF_BIAS + (size_t)G4*4)              // float [2][H]
#define OFF_BAR   (OFF_HBUF + (size_t)2*HID*4)           // unsigned
#define SCRATCH_BYTES (OFF_BAR + 256)

__device__ __align__(256) unsigned char g_scratch[SCRATCH_BYTES];

__device__ __forceinline__ float sigf(float x){ return 1.0f / (1.0f + __expf(-x)); }
__device__ __forceinline__ float2 h2f(unsigned u){
    __half2 h = *reinterpret_cast<__half2*>(&u);
    return __half22float2(h);
}

// ---------------- conversion / setup kernels ----------------
__global__ void f2h_split_kernel(const float* __restrict__ in, __half* __restrict__ hi,
                                 __half* __restrict__ lo, int n){
    int i = (blockIdx.x * blockDim.x + threadIdx.x) * 4;
    int stride = gridDim.x * blockDim.x * 4;
    for (; i < n; i += stride){
        float4 v = *(const float4*)(in + i);
        __half h0 = __float2half_rn(v.x), h1 = __float2half_rn(v.y);
        __half h2 = __float2half_rn(v.z), h3 = __float2half_rn(v.w);
        ((__half2*)(hi + i))[0] = __halves2half2(h0, h1);
        ((__half2*)(hi + i))[1] = __halves2half2(h2, h3);
        ((__half2*)(lo + i))[0] = __halves2half2(
            __float2half_rn(v.x - __half2float(h0)), __float2half_rn(v.y - __half2float(h1)));
        ((__half2*)(lo + i))[1] = __halves2half2(
            __float2half_rn(v.z - __half2float(h2)), __float2half_rn(v.w - __half2float(h3)));
    }
}

__global__ void bias_kernel(const float* __restrict__ a, const float* __restrict__ b,
                            float* __restrict__ o){
    int i = blockIdx.x * blockDim.x + threadIdx.x;
    if (i < G4) o[i] = a[i] + b[i];
}

__global__ void reset_kernel(unsigned* bar){ *bar = 0u; }

// ---------------- fp16 NT GEMM with mma.sync (f32 accum) ----------------
__device__ __forceinline__ void cp_async16(void* smem, const void* g){
    unsigned s = (unsigned)__cvta_generic_to_shared(smem);
    asm volatile("cp.async.cg.shared.global [%0], [%1], 16;\n" :: "r"(s), "l"(g));
}
__device__ __forceinline__ void cp_commit(){ asm volatile("cp.async.commit_group;\n"); }
template<int N> __device__ __forceinline__ void cp_wait(){
    asm volatile("cp.async.wait_group %0;\n" :: "n"(N));
}
__device__ __forceinline__ void mma16816(float* c, const unsigned* a, const unsigned* b){
    asm volatile(
        "mma.sync.aligned.m16n8k16.row.col.f32.f16.f16.f32 "
        "{%0,%1,%2,%3}, {%4,%5,%6,%7}, {%8,%9}, {%0,%1,%2,%3};"
        : "+f"(c[0]), "+f"(c[1]), "+f"(c[2]), "+f"(c[3])
        : "r"(a[0]), "r"(a[1]), "r"(a[2]), "r"(a[3]), "r"(b[0]), "r"(b[1]));
}

#define GSTRIDE 40   // halves per smem row: 32 data + 8 pad = 80B (16B-aligned, conflict-free)

// C[M,N] = A[M,K]*B[N,K]^T (+bias | +=C). dims %128==0, K%32==0.
template<int SIG, int ACC>
__global__ __launch_bounds__(256, 1)
void gemm_nt_kernel(const __half* __restrict__ A, const __half* __restrict__ B,
                    const float* __restrict__ bias, float* __restrict__ C,
                    int M, int N, int K){
    __shared__ __half As[2][128 * GSTRIDE];
    __shared__ __half Bs[2][128 * GSTRIDE];
    const int tid = threadIdx.x, wid = tid >> 5, l = tid & 31;
    const int wm = wid & 1, wn = wid >> 1;            // 2x4 warps, 64x32 warp tile
    const int m0 = blockIdx.y * 128, n0 = blockIdx.x * 128;

    float acc[4][4][4];
    #pragma unroll
    for (int i = 0; i < 4; ++i)
        #pragma unroll
        for (int j = 0; j < 4; ++j)
            #pragma unroll
            for (int q = 0; q < 4; ++q) acc[i][j][q] = 0.0f;

    const int NT = K / 32;
    auto load_stage = [&](int s, int kt){
        #pragma unroll
        for (int i = 0; i < 2; ++i){
            int c = tid + i * 256;
            int r = c >> 2, ch = c & 3;
            cp_async16(&As[s][r * GSTRIDE + ch * 8], A + (size_t)(m0 + r) * K + kt + ch * 8);
            cp_async16(&Bs[s][r * GSTRIDE + ch * 8], B + (size_t)(n0 + r) * K + kt + ch * 8);
        }
        cp_commit();
    };

    load_stage(0, 0);
    for (int t = 0; t < NT; ++t){
        if (t + 1 < NT){ load_stage((t + 1) & 1, (t + 1) * 32); cp_wait<1>(); }
        else           { cp_wait<0>(); }
        __syncthreads();
        const __half* Asb = As[t & 1];
        const __half* Bsb = Bs[t & 1];
        #pragma unroll
        for (int k16 = 0; k16 < 2; ++k16){
            unsigned a[4][4], b[4][2];
            const int cc = k16 * 16 + (l & 3) * 2;
            #pragma unroll
            for (int i = 0; i < 4; ++i){
                int r = wm * 64 + i * 16 + (l >> 2);
                a[i][0] = *(const unsigned*)(Asb + r * GSTRIDE + cc);
                a[i][1] = *(const unsigned*)(Asb + (r + 8) * GSTRIDE + cc);
                a[i][2] = *(const unsigned*)(Asb + r * GSTRIDE + cc + 8);
                a[i][3] = *(const unsigned*)(Asb + (r + 8) * GSTRIDE + cc + 8);
            }
            #pragma unroll
            for (int j = 0; j < 4; ++j){
                int r = wn * 32 + j * 8 + (l >> 2);
                b[j][0] = *(const unsigned*)(Bsb + r * GSTRIDE + cc);
                b[j][1] = *(const unsigned*)(Bsb + r * GSTRIDE + cc + 8);
            }
            #pragma unroll
            for (int i = 0; i < 4; ++i)
                #pragma unroll
                for (int j = 0; j < 4; ++j)
                    mma16816(acc[i][j], a[i], b[j]);
        }
        __syncthreads();
    }

    #pragma unroll
    for (int i = 0; i < 4; ++i){
        #pragma unroll
        for (int j = 0; j < 4; ++j){
            int rm = m0 + wm * 64 + i * 16 + (l >> 2);
            int cn = n0 + wn * 32 + j * 8 + (l & 3) * 2;
            float2* p0 = (float2*)(C + (size_t)rm * N + cn);
            float2* p1 = (float2*)(C + (size_t)(rm + 8) * N + cn);
            float v0, v1, v2, v3;
            if (ACC){
                float2 o0 = *p0, o1 = *p1;
                v0 = acc[i][j][0] + o0.x; v1 = acc[i][j][1] + o0.y;
                v2 = acc[i][j][2] + o1.x; v3 = acc[i][j][3] + o1.y;
            } else {
                float b0 = bias[cn], b1 = bias[cn + 1];
                v0 = acc[i][j][0] + b0; v1 = acc[i][j][1] + b1;
                v2 = acc[i][j][2] + b0; v3 = acc[i][j][3] + b1;
                if (SIG){ v0 = sigf(v0); v1 = sigf(v1); v2 = sigf(v2); v3 = sigf(v3); }
            }
            *p0 = make_float2(v0, v1);
            *p1 = make_float2(v2, v3);
        }
    }
}

// ---------------- persistent LSTM recurrence ----------------
// 148 CTAs (1/SM). CTA c owns h-elements [c*14, c*14+14); their 56 W_hh rows
// live in SMEM as fp16 (224KB). One warp per h-element computes the 4 gate
// dot products; c stays in a register; grid spin-barrier per timestep.
__global__ __launch_bounds__(RTHREADS, 1)
void lstm_rec_kernel(const float* __restrict__ Whh, const float* __restrict__ gx,
                     __half* __restrict__ hs, float* __restrict__ hbuf,
                     unsigned* __restrict__ bar){
    extern __shared__ uint4 smW[];                    // [56][256] uint4 = 2048 fp16/row
    unsigned* smw32 = (unsigned*)smW;
    const int tid = threadIdx.x;
    const int w = tid >> 5, l = tid & 31;
    const int cta = blockIdx.x;

    // load + convert this CTA's W_hh rows to fp16 in SMEM
    for (int idx = tid; idx < NROWS * 1024; idx += RTHREADS){
        int sr = idx >> 10, wc = idx & 1023;
        int e = cta * HPC + (sr >> 2);
        int gate = sr & 3;
        unsigned val = 0u;
        if (e < HID){
            const float2 f2 = *(const float2*)(Whh + (size_t)(gate * HID + e) * HID + 2 * wc);
            unsigned lo = (unsigned)__half_as_ushort(__float2half_rn(f2.x));
            unsigned hi = (unsigned)__half_as_ushort(__float2half_rn(f2.y));
            val = (hi << 16) | lo;
        }
        smw32[sr * 1024 + wc] = val;
    }
    if (tid < HPC){
        int e = cta * HPC + tid;
        if (e < HID) hbuf[e] = 0.0f;
    }
    __syncthreads();
    if (tid == 0){
        __threadfence();
        atomicAdd(bar, 1u);
        while (*(volatile unsigned*)bar < (unsigned)NCTA) { }
    }
    __syncthreads();

    const int e = cta * HPC + w;
    const bool active = (e < HID);
    const int w4 = w * 4;
    float c = 0.0f;

    #pragma unroll 1
    for (int t = 0; t < TT; ++t){
        const float* hr = hbuf + (t & 1) * HID;
        float*       hw = hbuf + ((t + 1) & 1) * HID;

        float gx0 = 0.f, gx1 = 0.f, gx2 = 0.f, gx3 = 0.f;
        if (active){
            const float* gp = gx + (size_t)t * G4 + e;
            gx0 = __ldcg(gp);
            gx1 = __ldcg(gp + HID);
            gx2 = __ldcg(gp + 2 * HID);
            gx3 = __ldcg(gp + 3 * HID);
        }

        // lane l covers h columns [8l+256j, 8l+256j+8), j=0..7
        float4 hv[16];
        #pragma unroll
        for (int j = 0; j < 8; ++j){
            hv[2 * j]     = __ldcg((const float4*)hr + 2 * l + 64 * j);
            hv[2 * j + 1] = __ldcg((const float4*)hr + 2 * l + 64 * j + 1);
        }

        float acc[4] = {0.f, 0.f, 0.f, 0.f};
        #pragma unroll
        for (int j = 0; j < 8; ++j){
            float4 ha = hv[2 * j], hb = hv[2 * j + 1];
            #pragma unroll
            for (int g = 0; g < 4; ++g){
                uint4 wv = smW[(w4 + g) * 256 + l + 32 * j];
                float2 w0 = h2f(wv.x), w1 = h2f(wv.y), w2 = h2f(wv.z), w3 = h2f(wv.w);
                float s = acc[g];
                s += w0.x * ha.x;  s += w0.y * ha.y;
                s += w1.x * ha.z;  s += w1.y * ha.w;
                s += w2.x * hb.x;  s += w2.y * hb.y;
                s += w3.x * hb.z;  s += w3.y * hb.w;
                acc[g] = s;
            }
        }
        #pragma unroll
        for (int off = 16; off; off >>= 1){
            acc[0] += __shfl_xor_sync(0xffffffffu, acc[0], off);
            acc[1] += __shfl_xor_sync(0xffffffffu, acc[1], off);
            acc[2] += __shfl_xor_sync(0xffffffffu, acc[2], off);
            acc[3] += __shfl_xor_sync(0xffffffffu, acc[3], off);
        }

        if (active && l == 0){
            float gi = acc[0] + gx0;
            float gf = acc[1] + gx1;
            float gg = acc[2] + gx2;
            float go = acc[3] + gx3;
            float ig = sigf(gi), fg = sigf(gf), og = sigf(go);
            float gt = tanhf(gg);
            c = fg * c + ig * gt;
            float hn = og * tanhf(c);
            hw[e] = hn;
            hs[(size_t)t * HID + e] = __float2half(hn);
            __threadfence();
        }

        __syncthreads();
        if (tid == 0){
            __threadfence();
            atomicAdd(bar, 1u);
            unsigned target = (unsigned)(t + 2) * (unsigned)NCTA;
            while (*(volatile unsigned*)bar < target) { }
        }
        __syncthreads();
    }
}

// ---------------- launch ----------------
extern "C" void kernel_launch(void* const* d_in, const int* in_sizes, int n_in,
                              void* d_out, int out_size){
    const float* x    = (const float*)d_in[0];
    const float* W_ih = (const float*)d_in[1];
    const float* W_hh = (const float*)d_in[2];
    const float* b_ih = (const float*)d_in[3];
    const float* b_hh = (const float*)d_in[4];
    const float* Wo   = (const float*)d_in[5];
    const float* bo   = (const float*)d_in[6];
    float* out = (float*)d_out;

    unsigned char* base = nullptr;
    cudaGetSymbolAddress((void**)&base, g_scratch);
    float*    gx   = (float*)(base + OFF_GX);
    __half*   xh   = (__half*)(base + OFF_XH);
    __half*   xl   = (__half*)(base + OFF_XL);
    __half*   wih  = (__half*)(base + OFF_WIH);
    __half*   wil  = (__half*)(base + OFF_WIL);
    __half*   wo   = (__half*)(base + OFF_WO);
    __half*   wol  = (__half*)(base + OFF_WOL);
    __half*   hsb  = (__half*)(base + OFF_HS);
    float*    bias = (float*)(base + OFF_BIAS);
    float*    hbuf = (float*)(base + OFF_HBUF);
    unsigned* bar  = (unsigned*)(base + OFF_BAR);

    cudaFuncSetAttribute(lstm_rec_kernel,
                         cudaFuncAttributeMaxDynamicSharedMemorySize, REC_SMEM);

    reset_kernel<<<1, 1>>>(bar);
    bias_kernel<<<G4 / 256, 256>>>(b_ih, b_hh, bias);
    f2h_split_kernel<<<1024, 256>>>(x,    xh,  xl,  TT * INW);
    f2h_split_kernel<<<1024, 256>>>(W_ih, wih, wil, G4 * INW);
    f2h_split_kernel<<<1024, 256>>>(Wo,   wo,  wol, INW * HID);

    dim3 g1(G4 / 128, TT / 128);
    gemm_nt_kernel<0, 0><<<g1, 256>>>(xh, wih, bias, gx, TT, G4, INW);
    gemm_nt_kernel<0, 1><<<g1, 256>>>(xl, wih, bias, gx, TT, G4, INW);
    gemm_nt_kernel<0, 1><<<g1, 256>>>(xh, wil, bias, gx, TT, G4, INW);

    lstm_rec_kernel<<<NCTA, RTHREADS, REC_SMEM>>>(W_hh, gx, hsb, hbuf, bar);

    dim3 g2(INW / 128, TT / 128);
    gemm_nt_kernel<1, 0><<<g2, 256>>>(hsb, wo, bo, out, TT, INW, HID);
}